// round 2
// baseline (speedup 1.0000x reference)
#include <cuda_runtime.h>
#include <math.h>
#include <stdint.h>

// Problem constants (B=2, S=1024, D=1024, V=32000, K=16)
#define N_ROWS 2048
#define DIM    1024
#define VOCAB  32000
#define TOPK   16
#define KTOT   2048   // 2*DIM
#define DTILES 8      // DIM/128

// Scratch (device globals; no allocation allowed)
__device__ __align__(128) float g_merged[N_ROWS * DIM];
__device__ __align__(128) float g_probs[N_ROWS * TOPK];
__device__ __align__(128) float g_zpart[N_ROWS * DTILES];

// ---------------------------------------------------------------------------
// Kernel A: per-row prep. mean_h -> bandwidth -> sparse_probs -> merged.
// One block per row; searched_hidden row (16x1024 f32 = 64KB) staged in smem.
// ---------------------------------------------------------------------------
__global__ __launch_bounds__(256) void prep_kernel(
    const float* __restrict__ hidden,
    const float* __restrict__ dist,
    const float* __restrict__ sh,
    const float* __restrict__ bW,
    const float* __restrict__ bb)
{
    const int n = blockIdx.x;
    extern __shared__ float s_sh[];            // TOPK*DIM floats
    __shared__ float s_probs[TOPK];
    __shared__ float sred[8];

    const float* shrow = sh + (size_t)n * (TOPK * DIM);
    const float* hrow  = hidden + (size_t)n * DIM;
    const int tid = threadIdx.x;

    // dot([h ; mean_k sh], bW): accumulate sh part (vs bW[DIM+d]) and h part.
    float acc_sh = 0.f, acc_h = 0.f;
    for (int i = tid; i < TOPK * DIM; i += 256) {
        float v = shrow[i];
        s_sh[i] = v;
        acc_sh += v * __ldg(&bW[DIM + (i & (DIM - 1))]);
    }
    for (int d = tid; d < DIM; d += 256)
        acc_h += hrow[d] * __ldg(&bW[d]);

    float acc = acc_h + acc_sh * (1.f / (float)TOPK);
    #pragma unroll
    for (int o = 16; o > 0; o >>= 1)
        acc += __shfl_xor_sync(0xffffffffu, acc, o);
    if ((tid & 31) == 0) sred[tid >> 5] = acc;
    __syncthreads();

    if (tid == 0) {
        float tot = 0.f;
        #pragma unroll
        for (int i = 0; i < 8; i++) tot += sred[i];
        float bwv = expf(tot + bb[0]);

        // softmax over K=16 of -dist/bandwidth
        const float* dr = dist + (size_t)n * TOPK;
        float x[TOPK];
        float mx = -1e30f;
        #pragma unroll
        for (int k = 0; k < TOPK; k++) { x[k] = -dr[k] / bwv; mx = fmaxf(mx, x[k]); }
        float s = 0.f;
        #pragma unroll
        for (int k = 0; k < TOPK; k++) { x[k] = expf(x[k] - mx); s += x[k]; }
        float inv = 1.f / s;
        #pragma unroll
        for (int k = 0; k < TOPK; k++) {
            float p = x[k] * inv;
            s_probs[k] = p;
            g_probs[(size_t)n * TOPK + k] = p;
        }
    }
    __syncthreads();

    // merged[d] = sum_k p_k * sh[k,d]
    for (int d = tid; d < DIM; d += 256) {
        float m = 0.f;
        #pragma unroll
        for (int k = 0; k < TOPK; k++)
            m = fmaf(s_probs[k], s_sh[k * DIM + d], m);
        g_merged[(size_t)n * DIM + d] = m;
    }
}

// ---------------------------------------------------------------------------
// Kernel B: fused MLP. mw_hid = relu([h;merged] @ mW1^T + mb1);
// zpart[n][dTile] = sum_{d in tile} mw_hid[n,d]*mW2[d].
// SIMT fp32 GEMM, 128x128 tile, K-chunk 32, f32x2 packed FMA (FFMA2).
// ---------------------------------------------------------------------------
__device__ __forceinline__ unsigned long long pack2(float lo, float hi) {
    unsigned long long r;
    asm("mov.b64 %0, {%1, %2};" : "=l"(r)
        : "r"(__float_as_uint(lo)), "r"(__float_as_uint(hi)));
    return r;
}
__device__ __forceinline__ void ffma2(unsigned long long& c,
                                      unsigned long long a,
                                      unsigned long long b) {
    asm("fma.rn.f32x2 %0, %1, %2, %0;" : "+l"(c) : "l"(a), "l"(b));
}

__global__ __launch_bounds__(256) void gemm_kernel(
    const float* __restrict__ hidden,
    const float* __restrict__ mW1,
    const float* __restrict__ mb1,
    const float* __restrict__ mW2)
{
    __shared__ float As[32][132];   // [k][row], pitch 132 keeps float4 alignment
    __shared__ float Bs[32][132];   // [k][d]

    const int tid = threadIdx.x;
    const int rowTile = blockIdx.x;          // 0..15
    const int dTile   = blockIdx.y;          // 0..7
    const int tx = tid & 15, ty = tid >> 4;  // micro-tile coords
    const int kq = tid & 7,  rb = tid >> 3;  // load coords

    unsigned long long acc[8][4];
    #pragma unroll
    for (int r = 0; r < 8; r++)
        #pragma unroll
        for (int c = 0; c < 4; c++) acc[r][c] = 0ull;

    const float* Bbase = mW1 + (size_t)dTile * 128 * KTOT;

    for (int k0 = 0; k0 < KTOT; k0 += 32) {
        // virtual concat [hidden ; merged]: both halves have row stride DIM
        const float* Aseg = (k0 < DIM) ? (hidden + k0) : (g_merged + (k0 - DIM));
        const float* Bseg = Bbase + k0;

        #pragma unroll
        for (int it = 0; it < 4; it++) {
            int r = rb + 32 * it;
            float4 va = *(const float4*)(Aseg + (size_t)(rowTile * 128 + r) * DIM + kq * 4);
            float4 vb = *(const float4*)(Bseg + (size_t)r * KTOT + kq * 4);
            As[kq * 4 + 0][r] = va.x; As[kq * 4 + 1][r] = va.y;
            As[kq * 4 + 2][r] = va.z; As[kq * 4 + 3][r] = va.w;
            Bs[kq * 4 + 0][r] = vb.x; Bs[kq * 4 + 1][r] = vb.y;
            Bs[kq * 4 + 2][r] = vb.z; Bs[kq * 4 + 3][r] = vb.w;
        }
        __syncthreads();

        #pragma unroll
        for (int kk = 0; kk < 32; kk++) {
            float4 a0 = *(const float4*)&As[kk][ty * 8];
            float4 a1 = *(const float4*)&As[kk][ty * 8 + 4];
            float4 b0 = *(const float4*)&Bs[kk][tx * 8];
            float4 b1 = *(const float4*)&Bs[kk][tx * 8 + 4];
            unsigned long long bp[4] = {
                pack2(b0.x, b0.y), pack2(b0.z, b0.w),
                pack2(b1.x, b1.y), pack2(b1.z, b1.w)
            };
            float ar[8] = { a0.x, a0.y, a0.z, a0.w, a1.x, a1.y, a1.z, a1.w };
            #pragma unroll
            for (int r = 0; r < 8; r++) {
                unsigned long long ap = pack2(ar[r], ar[r]);
                #pragma unroll
                for (int c = 0; c < 4; c++) ffma2(acc[r][c], ap, bp[c]);
            }
        }
        __syncthreads();
    }

    // Epilogue: bias + relu + dot with mW2 within this d-tile, reduce over tx.
    const int d0 = dTile * 128 + tx * 8;
    float4 bi0 = *(const float4*)&mb1[d0];
    float4 bi1 = *(const float4*)&mb1[d0 + 4];
    float4 w0  = *(const float4*)&mW2[d0];
    float4 w1  = *(const float4*)&mW2[d0 + 4];
    float bia[8] = { bi0.x, bi0.y, bi0.z, bi0.w, bi1.x, bi1.y, bi1.z, bi1.w };
    float ww[8]  = { w0.x,  w0.y,  w0.z,  w0.w,  w1.x,  w1.y,  w1.z,  w1.w };

    #pragma unroll
    for (int r = 0; r < 8; r++) {
        float z = 0.f;
        #pragma unroll
        for (int c = 0; c < 4; c++) {
            float lo = __uint_as_float((unsigned)(acc[r][c] & 0xffffffffu));
            float hi = __uint_as_float((unsigned)(acc[r][c] >> 32));
            float h0 = fmaxf(lo + bia[2 * c], 0.f);
            float h1 = fmaxf(hi + bia[2 * c + 1], 0.f);
            z = fmaf(h0, ww[2 * c], z);
            z = fmaf(h1, ww[2 * c + 1], z);
        }
        #pragma unroll
        for (int o = 8; o > 0; o >>= 1)
            z += __shfl_down_sync(0xffffffffu, z, o, 16);
        if (tx == 0)
            g_zpart[(size_t)(rowTile * 128 + ty * 8 + r) * DTILES + dTile] = z;
    }
}

// ---------------------------------------------------------------------------
// Kernel C: per-row output. One block per row, logits staged in 125KB smem.
// out[v] = lg[v] - max + log((1-m)/sumexp) for all v; <=16 scatter fixups.
// Token dtype (int32 vs int64) is probed in-kernel: for int64 data every odd
// 32-bit word is a zero high-half; for int32 data that pattern has p~(1/V)^16.
// ---------------------------------------------------------------------------
__global__ __launch_bounds__(1024) void out_kernel(
    const float* __restrict__ logits,
    const void* __restrict__ tok,
    const float* __restrict__ mb2,
    float* __restrict__ out)
{
    const int n = blockIdx.x;
    extern __shared__ float slg[];                 // VOCAB floats
    __shared__ float sred[32];
    __shared__ float s_max, s_sum, s_m;
    __shared__ int   s_uidx[TOPK];
    __shared__ float s_uval[TOPK];
    __shared__ int   s_ucnt;

    const int tid  = threadIdx.x;
    const int lane = tid & 31, wid = tid >> 5;
    const float* lrow = logits + (size_t)n * VOCAB;
    float*       orow = out    + (size_t)n * VOCAB;

    // Pass 1: stage logits row in smem, track max.
    float mx = -1e30f;
    const float4* l4 = (const float4*)lrow;
    float4*       s4 = (float4*)slg;
    for (int i = tid; i < VOCAB / 4; i += 1024) {
        float4 v = l4[i];
        s4[i] = v;
        mx = fmaxf(mx, fmaxf(fmaxf(v.x, v.y), fmaxf(v.z, v.w)));
    }
    #pragma unroll
    for (int o = 16; o > 0; o >>= 1)
        mx = fmaxf(mx, __shfl_xor_sync(0xffffffffu, mx, o));
    if (lane == 0) sred[wid] = mx;
    __syncthreads();
    if (tid < 32) {
        float v = sred[tid];
        #pragma unroll
        for (int o = 16; o > 0; o >>= 1)
            v = fmaxf(v, __shfl_xor_sync(0xffffffffu, v, o));
        if (tid == 0) s_max = v;
    }
    __syncthreads();

    // Pass 2: sum of exp from smem.
    float fm = s_max;
    float sm = 0.f;
    for (int i = tid; i < VOCAB; i += 1024)
        sm += expf(slg[i] - fm);
    #pragma unroll
    for (int o = 16; o > 0; o >>= 1)
        sm += __shfl_xor_sync(0xffffffffu, sm, o);
    __syncthreads();              // sred reuse
    if (lane == 0) sred[wid] = sm;
    __syncthreads();
    if (tid < 32) {
        float v = sred[tid];
        #pragma unroll
        for (int o = 16; o > 0; o >>= 1)
            v += __shfl_xor_sync(0xffffffffu, v, o);
        if (tid == 0) s_sum = v;
    }

    // Thread 0: dtype probe + mixing weight + dedupe scattered top-k entries.
    if (tid == 0) {
        // Probe token dtype once (row 0's first 16 odd 32-bit words).
        const int* t32 = (const int*)tok;
        int is64 = 1;
        #pragma unroll
        for (int k = 0; k < TOPK; k++)
            if (t32[2 * k + 1] != 0) is64 = 0;

        float z = mb2[0];
        #pragma unroll
        for (int j = 0; j < DTILES; j++) z += g_zpart[(size_t)n * DTILES + j];
        float m = 1.f / (1.f + expf(-z));
        s_m = m;

        const long long* t64 = (const long long*)tok;
        int cnt = 0;
        #pragma unroll
        for (int k = 0; k < TOPK; k++) {
            int idx = is64 ? (int)t64[(size_t)n * TOPK + k]
                           : t32[(size_t)n * TOPK + k];
            idx = min(max(idx, 0), VOCAB - 1);   // defensive clamp
            float val = m * g_probs[(size_t)n * TOPK + k];
            int j = 0;
            for (; j < cnt; j++) if (s_uidx[j] == idx) break;
            if (j < cnt) s_uval[j] += val;
            else { s_uidx[cnt] = idx; s_uval[cnt] = val; cnt++; }
        }
        s_ucnt = cnt;
    }
    __syncthreads();

    // Main write: log((1-m)*softmax) = lg - max + log((1-m)/sumexp)
    const float logc = logf((1.f - s_m) / s_sum);
    for (int i = tid; i < VOCAB / 4; i += 1024) {
        float4 v = s4[i];
        v.x = v.x - fm + logc;
        v.y = v.y - fm + logc;
        v.z = v.z - fm + logc;
        v.w = v.w - fm + logc;
        ((float4*)orow)[i] = v;
    }
    __syncthreads();

    // Fixups at scattered token indices.
    if (tid < s_ucnt) {
        int vi = s_uidx[tid];
        float p = expf(slg[vi] - fm) / s_sum;
        orow[vi] = logf((1.f - s_m) * p + s_uval[tid]);
    }
}

// ---------------------------------------------------------------------------
// Host: resolve input ordering purely from element counts (robust to dict or
// alphabetical metadata order), then launch the 3-kernel pipeline.
// ---------------------------------------------------------------------------
extern "C" void kernel_launch(void* const* d_in, const int* in_sizes, int n_in,
                              void* d_out, int out_size)
{
    // Expected element counts:
    //   hidden 2097152 | logits 65536000 | distances 32768 | searched 33554432
    //   tok 32768 | bW 2048 | bb 1 | mW1 2097152 | mb1 1024 | mW2 1024 | mb2 1
    int i_logits = -1, i_sh = -1, i_bW = -1;
    int p2m[2] = {-1, -1};  int n2m = 0;   // 2097152: hidden, mW1
    int p32k[2] = {-1, -1}; int n32k = 0;  // 32768: distances, tok
    int p1k[2] = {-1, -1};  int n1k = 0;   // 1024: mb1/mW2 (order varies)
    int p1[2] = {-1, -1};   int n1 = 0;    // 1: bb, mb2

    for (int i = 0; i < n_in; i++) {
        switch (in_sizes[i]) {
            case 65536000: i_logits = i; break;
            case 33554432: i_sh = i; break;
            case 2048:     i_bW = i; break;
            case 2097152:  if (n2m < 2) p2m[n2m++] = i; break;
            case 32768:    if (n32k < 2) p32k[n32k++] = i; break;
            case 1024:     if (n1k < 2) p1k[n1k++] = i; break;
            case 1:        if (n1 < 2) p1[n1++] = i; break;
            default: break;
        }
    }
    // hidden precedes mW1, distances precede tok, bb precedes mb2 in BOTH
    // dict and alphabetical orders. mb1/mW2 flip: alphabetical puts mW2 first.
    const bool alpha = (i_bW >= 0 && i_logits >= 0 && i_bW < i_logits);
    const int i_hidden = p2m[0],  i_mW1 = p2m[1];
    const int i_dist   = p32k[0], i_tok = p32k[1];
    const int i_bb     = p1[0],   i_mb2 = p1[1];
    const int i_mb1    = alpha ? p1k[1] : p1k[0];
    const int i_mW2    = alpha ? p1k[0] : p1k[1];

    const float* hidden = (const float*)d_in[i_hidden];
    const float* logits = (const float*)d_in[i_logits];
    const float* dist   = (const float*)d_in[i_dist];
    const float* sh     = (const float*)d_in[i_sh];
    const void*  tok    = d_in[i_tok];
    const float* bW     = (const float*)d_in[i_bW];
    const float* bb     = (const float*)d_in[i_bb];
    const float* mW1    = (const float*)d_in[i_mW1];
    const float* mb1    = (const float*)d_in[i_mb1];
    const float* mW2    = (const float*)d_in[i_mW2];
    const float* mb2    = (const float*)d_in[i_mb2];
    float*       out    = (float*)d_out;

    const int smA = TOPK * DIM * sizeof(float);   // 64 KB
    const int smC = VOCAB * sizeof(float);        // 125 KB
    cudaFuncSetAttribute(prep_kernel, cudaFuncAttributeMaxDynamicSharedMemorySize, smA);
    cudaFuncSetAttribute(out_kernel,  cudaFuncAttributeMaxDynamicSharedMemorySize, smC);

    prep_kernel<<<N_ROWS, 256, smA>>>(hidden, dist, sh, bW, bb);
    gemm_kernel<<<dim3(16, 8), 256>>>(hidden, mW1, mb1, mW2);
    out_kernel<<<N_ROWS, 1024, smC>>>(logits, tok, mb2, out);
}

// round 3
// speedup vs baseline: 1.2926x; 1.2926x over previous
#include <cuda_runtime.h>
#include <mma.h>
#include <math.h>
#include <stdint.h>

using namespace nvcuda;

// Problem constants (B=2, S=1024, D=1024, V=32000, K=16)
#define N_ROWS 2048
#define DIM    1024
#define VOCAB  32000
#define TOPK   16
#define KTOT   2048   // 2*DIM
#define DTILES 8      // DIM/128

// Scratch (device globals; no allocation allowed)
__device__ __align__(128) float g_merged[N_ROWS * DIM];
__device__ __align__(128) float g_probs[N_ROWS * TOPK];
__device__ __align__(128) float g_zpart[N_ROWS * DTILES];

// ---------------------------------------------------------------------------
// Kernel A: per-row prep. mean_h -> bandwidth -> sparse_probs -> merged.
// One block per row; searched_hidden row (16x1024 f32 = 64KB) staged in smem
// via float4 loads; 512 threads for occupancy + MLP.
// ---------------------------------------------------------------------------
__global__ __launch_bounds__(512) void prep_kernel(
    const float* __restrict__ hidden,
    const float* __restrict__ dist,
    const float* __restrict__ sh,
    const float* __restrict__ bW,
    const float* __restrict__ bb)
{
    const int n = blockIdx.x;
    extern __shared__ float s_sh[];            // TOPK*DIM floats (64KB)
    __shared__ float s_probs[TOPK];
    __shared__ float sred[16];

    const int tid = threadIdx.x;
    const float4* sh4 = (const float4*)(sh + (size_t)n * (TOPK * DIM));
    float4* s4 = (float4*)s_sh;

    // Stage sh row; accumulate dot(mean_k sh, bW[DIM:]) on the fly.
    float acc = 0.f;
    #pragma unroll 2
    for (int i = tid; i < TOPK * DIM / 4; i += 512) {
        float4 v = sh4[i];
        s4[i] = v;
        int base = (4 * i) & (DIM - 1);
        acc += v.x * __ldg(&bW[DIM + base])     + v.y * __ldg(&bW[DIM + base + 1])
             + v.z * __ldg(&bW[DIM + base + 2]) + v.w * __ldg(&bW[DIM + base + 3]);
    }
    acc *= (1.f / (float)TOPK);

    const float4* h4 = (const float4*)(hidden + (size_t)n * DIM);
    for (int i = tid; i < DIM / 4; i += 512) {
        float4 v = h4[i];
        int base = 4 * i;
        acc += v.x * __ldg(&bW[base])     + v.y * __ldg(&bW[base + 1])
             + v.z * __ldg(&bW[base + 2]) + v.w * __ldg(&bW[base + 3]);
    }

    #pragma unroll
    for (int o = 16; o > 0; o >>= 1)
        acc += __shfl_xor_sync(0xffffffffu, acc, o);
    if ((tid & 31) == 0) sred[tid >> 5] = acc;
    __syncthreads();

    if (tid == 0) {
        float tot = 0.f;
        #pragma unroll
        for (int i = 0; i < 16; i++) tot += sred[i];
        float bwv = expf(tot + bb[0]);

        // softmax over K=16 of -dist/bandwidth
        const float* dr = dist + (size_t)n * TOPK;
        float x[TOPK];
        float mx = -1e30f;
        #pragma unroll
        for (int k = 0; k < TOPK; k++) { x[k] = -dr[k] / bwv; mx = fmaxf(mx, x[k]); }
        float s = 0.f;
        #pragma unroll
        for (int k = 0; k < TOPK; k++) { x[k] = expf(x[k] - mx); s += x[k]; }
        float inv = 1.f / s;
        #pragma unroll
        for (int k = 0; k < TOPK; k++) {
            float p = x[k] * inv;
            s_probs[k] = p;
            g_probs[(size_t)n * TOPK + k] = p;
        }
    }
    __syncthreads();

    // merged[d] = sum_k p_k * sh[k,d], vectorized
    float4* m4 = (float4*)(g_merged + (size_t)n * DIM);
    for (int i = tid; i < DIM / 4; i += 512) {
        float4 m = make_float4(0.f, 0.f, 0.f, 0.f);
        #pragma unroll
        for (int k = 0; k < TOPK; k++) {
            float p = s_probs[k];
            float4 v = s4[k * (DIM / 4) + i];
            m.x = fmaf(p, v.x, m.x); m.y = fmaf(p, v.y, m.y);
            m.z = fmaf(p, v.z, m.z); m.w = fmaf(p, v.w, m.w);
        }
        m4[i] = m;
    }
}

// ---------------------------------------------------------------------------
// Kernel B: fused MLP on tf32 tensor cores (wmma m16n16k8).
// C[n][d] = [h;merged] @ mW1^T; epilogue relu(C+mb1)*mW2 reduced over the
// 128-d tile -> g_zpart[n][dTile]. CTA tile 128x128, 8 warps (2M x 4N),
// warp tile 64x32. K staged 32 at a time in smem.
// ---------------------------------------------------------------------------
#define ASTRIDE 36   // smem pitch (floats), mult of 4 for wmma ldm

__global__ __launch_bounds__(256) void gemm_kernel(
    const float* __restrict__ hidden,
    const float* __restrict__ mW1,
    const float* __restrict__ mb1,
    const float* __restrict__ mW2)
{
    __shared__ float buf[2 * 128 * ASTRIDE];   // 36 KB; reused by epilogue
    float* As = buf;                    // [128][ASTRIDE]
    float* Bs = buf + 128 * ASTRIDE;    // [128][ASTRIDE]

    const int tid  = threadIdx.x;
    const int wid  = tid >> 5, lane = tid & 31;
    const int rowTile = blockIdx.x;     // 0..15
    const int dTile   = blockIdx.y;     // 0..7
    const int warpM = wid >> 2;         // 0..1 (64 rows each)
    const int warpN = wid & 3;          // 0..3 (32 cols each)

    wmma::fragment<wmma::accumulator, 16, 16, 8, float> c[4][2];
    #pragma unroll
    for (int mi = 0; mi < 4; mi++)
        #pragma unroll
        for (int ni = 0; ni < 2; ni++)
            wmma::fill_fragment(c[mi][ni], 0.f);

    for (int k0 = 0; k0 < KTOT; k0 += 32) {
        const float* Aseg = (k0 < DIM) ? (hidden + k0) : (g_merged + (k0 - DIM));
        #pragma unroll
        for (int it = 0; it < 4; it++) {
            int idx = tid + 256 * it;            // 0..1023
            int r = idx >> 3, kq = idx & 7;
            float4 va = *(const float4*)(Aseg + (size_t)(rowTile * 128 + r) * DIM + kq * 4);
            float4 vb = *(const float4*)(mW1 + (size_t)(dTile * 128 + r) * KTOT + k0 + kq * 4);
            va.x = wmma::__float_to_tf32(va.x); va.y = wmma::__float_to_tf32(va.y);
            va.z = wmma::__float_to_tf32(va.z); va.w = wmma::__float_to_tf32(va.w);
            vb.x = wmma::__float_to_tf32(vb.x); vb.y = wmma::__float_to_tf32(vb.y);
            vb.z = wmma::__float_to_tf32(vb.z); vb.w = wmma::__float_to_tf32(vb.w);
            *(float4*)(As + r * ASTRIDE + kq * 4) = va;
            *(float4*)(Bs + r * ASTRIDE + kq * 4) = vb;
        }
        __syncthreads();

        #pragma unroll
        for (int kk = 0; kk < 4; kk++) {
            wmma::fragment<wmma::matrix_a, 16, 16, 8, wmma::precision::tf32, wmma::row_major> a[4];
            wmma::fragment<wmma::matrix_b, 16, 16, 8, wmma::precision::tf32, wmma::col_major> b[2];
            #pragma unroll
            for (int mi = 0; mi < 4; mi++)
                wmma::load_matrix_sync(a[mi], As + (warpM * 64 + mi * 16) * ASTRIDE + kk * 8, ASTRIDE);
            #pragma unroll
            for (int ni = 0; ni < 2; ni++)
                wmma::load_matrix_sync(b[ni], Bs + (warpN * 32 + ni * 16) * ASTRIDE + kk * 8, ASTRIDE);
            #pragma unroll
            for (int mi = 0; mi < 4; mi++)
                #pragma unroll
                for (int ni = 0; ni < 2; ni++)
                    wmma::mma_sync(c[mi][ni], a[mi], b[ni], c[mi][ni]);
        }
        __syncthreads();   // also protects buf reuse by epilogue
    }

    // Epilogue: per-warp 16x16 frags -> smem scratch -> relu+dot(mW2) rowsum.
    float* scr   = buf + wid * 320;        // [16][20] per warp
    float* zrows = buf + 8 * 320;          // [128][4]

    float zacc[4] = {0.f, 0.f, 0.f, 0.f};
    const int r16 = lane & 15, ch = (lane >> 4) * 8;
    #pragma unroll
    for (int mi = 0; mi < 4; mi++) {
        #pragma unroll
        for (int ni = 0; ni < 2; ni++) {
            wmma::store_matrix_sync(scr, c[mi][ni], 20, wmma::mem_row_major);
            __syncwarp();
            int gc0 = dTile * 128 + warpN * 32 + ni * 16 + ch;
            float z = 0.f;
            #pragma unroll
            for (int cc = 0; cc < 8; cc++) {
                float v = scr[r16 * 20 + ch + cc] + __ldg(&mb1[gc0 + cc]);
                z = fmaf(fmaxf(v, 0.f), __ldg(&mW2[gc0 + cc]), z);
            }
            z += __shfl_xor_sync(0xffffffffu, z, 16);
            zacc[mi] += z;          // valid in lanes 0..15
            __syncwarp();
        }
    }
    if (lane < 16) {
        #pragma unroll
        for (int mi = 0; mi < 4; mi++)
            zrows[(warpM * 64 + mi * 16 + lane) * 4 + warpN] = zacc[mi];
    }
    __syncthreads();
    if (tid < 128) {
        float z = zrows[tid * 4 + 0] + zrows[tid * 4 + 1]
                + zrows[tid * 4 + 2] + zrows[tid * 4 + 3];
        g_zpart[(size_t)(rowTile * 128 + tid) * DTILES + dTile] = z;
    }
}

// ---------------------------------------------------------------------------
// Kernel C: per-row output. One block per row, logits staged in 125KB smem.
// out[v] = lg[v] - max + log((1-m)/sumexp) for all v; <=16 scatter fixups.
// Token dtype (int32 vs int64) probed in-kernel.
// ---------------------------------------------------------------------------
__global__ __launch_bounds__(1024) void out_kernel(
    const float* __restrict__ logits,
    const void* __restrict__ tok,
    const float* __restrict__ mb2,
    float* __restrict__ out)
{
    const int n = blockIdx.x;
    extern __shared__ float slg[];                 // VOCAB floats
    __shared__ float sred[32];
    __shared__ float s_max, s_sum, s_m;
    __shared__ int   s_uidx[TOPK];
    __shared__ float s_uval[TOPK];
    __shared__ int   s_ucnt;

    const int tid  = threadIdx.x;
    const int lane = tid & 31, wid = tid >> 5;
    const float* lrow = logits + (size_t)n * VOCAB;
    float*       orow = out    + (size_t)n * VOCAB;

    // Pass 1: stage logits row in smem, track max.
    float mx = -1e30f;
    const float4* l4 = (const float4*)lrow;
    float4*       s4 = (float4*)slg;
    for (int i = tid; i < VOCAB / 4; i += 1024) {
        float4 v = l4[i];
        s4[i] = v;
        mx = fmaxf(mx, fmaxf(fmaxf(v.x, v.y), fmaxf(v.z, v.w)));
    }
    #pragma unroll
    for (int o = 16; o > 0; o >>= 1)
        mx = fmaxf(mx, __shfl_xor_sync(0xffffffffu, mx, o));
    if (lane == 0) sred[wid] = mx;
    __syncthreads();
    if (tid < 32) {
        float v = sred[tid];
        #pragma unroll
        for (int o = 16; o > 0; o >>= 1)
            v = fmaxf(v, __shfl_xor_sync(0xffffffffu, v, o));
        if (tid == 0) s_max = v;
    }
    __syncthreads();

    // Pass 2: sum of exp from smem.
    float fm = s_max;
    float sm = 0.f;
    for (int i = tid; i < VOCAB; i += 1024)
        sm += expf(slg[i] - fm);
    #pragma unroll
    for (int o = 16; o > 0; o >>= 1)
        sm += __shfl_xor_sync(0xffffffffu, sm, o);
    __syncthreads();              // sred reuse
    if (lane == 0) sred[wid] = sm;
    __syncthreads();
    if (tid < 32) {
        float v = sred[tid];
        #pragma unroll
        for (int o = 16; o > 0; o >>= 1)
            v += __shfl_xor_sync(0xffffffffu, v, o);
        if (tid == 0) s_sum = v;
    }

    // Thread 0: dtype probe + mixing weight + dedupe scattered top-k entries.
    if (tid == 0) {
        const int* t32 = (const int*)tok;
        int is64 = 1;
        #pragma unroll
        for (int k = 0; k < TOPK; k++)
            if (t32[2 * k + 1] != 0) is64 = 0;

        float z = mb2[0];
        #pragma unroll
        for (int j = 0; j < DTILES; j++) z += g_zpart[(size_t)n * DTILES + j];
        float m = 1.f / (1.f + expf(-z));
        s_m = m;

        const long long* t64 = (const long long*)tok;
        int cnt = 0;
        #pragma unroll
        for (int k = 0; k < TOPK; k++) {
            int idx = is64 ? (int)t64[(size_t)n * TOPK + k]
                           : t32[(size_t)n * TOPK + k];
            idx = min(max(idx, 0), VOCAB - 1);   // defensive clamp
            float val = m * g_probs[(size_t)n * TOPK + k];
            int j = 0;
            for (; j < cnt; j++) if (s_uidx[j] == idx) break;
            if (j < cnt) s_uval[j] += val;
            else { s_uidx[cnt] = idx; s_uval[cnt] = val; cnt++; }
        }
        s_ucnt = cnt;
    }
    __syncthreads();

    // Main write: log((1-m)*softmax) = lg - max + log((1-m)/sumexp)
    const float logc = logf((1.f - s_m) / s_sum);
    for (int i = tid; i < VOCAB / 4; i += 1024) {
        float4 v = s4[i];
        v.x = v.x - fm + logc;
        v.y = v.y - fm + logc;
        v.z = v.z - fm + logc;
        v.w = v.w - fm + logc;
        ((float4*)orow)[i] = v;
    }
    __syncthreads();

    // Fixups at scattered token indices.
    if (tid < s_ucnt) {
        int vi = s_uidx[tid];
        float p = expf(slg[vi] - fm) / s_sum;
        orow[vi] = logf((1.f - s_m) * p + s_uval[tid]);
    }
}

// ---------------------------------------------------------------------------
// Host: resolve input ordering purely from element counts (robust to dict or
// alphabetical metadata order), then launch the 3-kernel pipeline.
// ---------------------------------------------------------------------------
extern "C" void kernel_launch(void* const* d_in, const int* in_sizes, int n_in,
                              void* d_out, int out_size)
{
    int i_logits = -1, i_sh = -1, i_bW = -1;
    int p2m[2] = {-1, -1};  int n2m = 0;   // 2097152: hidden, mW1
    int p32k[2] = {-1, -1}; int n32k = 0;  // 32768: distances, tok
    int p1k[2] = {-1, -1};  int n1k = 0;   // 1024: mb1/mW2 (order varies)
    int p1[2] = {-1, -1};   int n1 = 0;    // 1: bb, mb2

    for (int i = 0; i < n_in; i++) {
        switch (in_sizes[i]) {
            case 65536000: i_logits = i; break;
            case 33554432: i_sh = i; break;
            case 2048:     i_bW = i; break;
            case 2097152:  if (n2m < 2) p2m[n2m++] = i; break;
            case 32768:    if (n32k < 2) p32k[n32k++] = i; break;
            case 1024:     if (n1k < 2) p1k[n1k++] = i; break;
            case 1:        if (n1 < 2) p1[n1++] = i; break;
            default: break;
        }
    }
    const bool alpha = (i_bW >= 0 && i_logits >= 0 && i_bW < i_logits);
    const int i_hidden = p2m[0],  i_mW1 = p2m[1];
    const int i_dist   = p32k[0], i_tok = p32k[1];
    const int i_bb     = p1[0],   i_mb2 = p1[1];
    const int i_mb1    = alpha ? p1k[1] : p1k[0];
    const int i_mW2    = alpha ? p1k[0] : p1k[1];

    const float* hidden = (const float*)d_in[i_hidden];
    const float* logits = (const float*)d_in[i_logits];
    const float* dist   = (const float*)d_in[i_dist];
    const float* sh     = (const float*)d_in[i_sh];
    const void*  tok    = d_in[i_tok];
    const float* bW     = (const float*)d_in[i_bW];
    const float* bb     = (const float*)d_in[i_bb];
    const float* mW1    = (const float*)d_in[i_mW1];
    const float* mb1    = (const float*)d_in[i_mb1];
    const float* mW2    = (const float*)d_in[i_mW2];
    const float* mb2    = (const float*)d_in[i_mb2];
    float*       out    = (float*)d_out;

    const int smA = TOPK * DIM * sizeof(float);   // 64 KB
    const int smC = VOCAB * sizeof(float);        // 125 KB
    cudaFuncSetAttribute(prep_kernel, cudaFuncAttributeMaxDynamicSharedMemorySize, smA);
    cudaFuncSetAttribute(out_kernel,  cudaFuncAttributeMaxDynamicSharedMemorySize, smC);

    prep_kernel<<<N_ROWS, 512, smA>>>(hidden, dist, sh, bW, bb);
    gemm_kernel<<<dim3(16, 8), 256>>>(hidden, mW1, mb1, mW2);
    out_kernel<<<N_ROWS, 1024, smC>>>(logits, tok, mb2, out);
}

// round 4
// speedup vs baseline: 1.6419x; 1.2702x over previous
#include <cuda_runtime.h>
#include <cuda_bf16.h>
#include <mma.h>
#include <math.h>
#include <stdint.h>

using namespace nvcuda;

// Problem constants (B=2, S=1024, D=1024, V=32000, K=16)
#define N_ROWS 2048
#define DIM    1024
#define VOCAB  32000
#define TOPK   16
#define KTOT   2048   // 2*DIM
#define DTILES 8      // DIM/128

// Scratch (device globals; no allocation allowed)
__device__ __align__(128) float g_merged[N_ROWS * DIM];
__device__ __align__(128) float g_probs[N_ROWS * TOPK];
__device__ __align__(128) float g_zpart[N_ROWS * DTILES];

// ---------------------------------------------------------------------------
// Kernel A: per-row prep. mean_h -> bandwidth -> sparse_probs -> merged.
// ---------------------------------------------------------------------------
__global__ __launch_bounds__(512) void prep_kernel(
    const float* __restrict__ hidden,
    const float* __restrict__ dist,
    const float* __restrict__ sh,
    const float* __restrict__ bW,
    const float* __restrict__ bb)
{
    const int n = blockIdx.x;
    extern __shared__ float s_sh[];            // TOPK*DIM floats (64KB)
    __shared__ float s_probs[TOPK];
    __shared__ float sred[16];

    const int tid = threadIdx.x;
    const float4* sh4 = (const float4*)(sh + (size_t)n * (TOPK * DIM));
    float4* s4 = (float4*)s_sh;

    float acc = 0.f;
    #pragma unroll 2
    for (int i = tid; i < TOPK * DIM / 4; i += 512) {
        float4 v = sh4[i];
        s4[i] = v;
        int base = (4 * i) & (DIM - 1);
        acc += v.x * __ldg(&bW[DIM + base])     + v.y * __ldg(&bW[DIM + base + 1])
             + v.z * __ldg(&bW[DIM + base + 2]) + v.w * __ldg(&bW[DIM + base + 3]);
    }
    acc *= (1.f / (float)TOPK);

    const float4* h4 = (const float4*)(hidden + (size_t)n * DIM);
    for (int i = tid; i < DIM / 4; i += 512) {
        float4 v = h4[i];
        int base = 4 * i;
        acc += v.x * __ldg(&bW[base])     + v.y * __ldg(&bW[base + 1])
             + v.z * __ldg(&bW[base + 2]) + v.w * __ldg(&bW[base + 3]);
    }

    #pragma unroll
    for (int o = 16; o > 0; o >>= 1)
        acc += __shfl_xor_sync(0xffffffffu, acc, o);
    if ((tid & 31) == 0) sred[tid >> 5] = acc;
    __syncthreads();

    if (tid == 0) {
        float tot = 0.f;
        #pragma unroll
        for (int i = 0; i < 16; i++) tot += sred[i];
        float bwv = expf(tot + bb[0]);

        const float* dr = dist + (size_t)n * TOPK;
        float x[TOPK];
        float mx = -1e30f;
        #pragma unroll
        for (int k = 0; k < TOPK; k++) { x[k] = -dr[k] / bwv; mx = fmaxf(mx, x[k]); }
        float s = 0.f;
        #pragma unroll
        for (int k = 0; k < TOPK; k++) { x[k] = expf(x[k] - mx); s += x[k]; }
        float inv = 1.f / s;
        #pragma unroll
        for (int k = 0; k < TOPK; k++) {
            float p = x[k] * inv;
            s_probs[k] = p;
            g_probs[(size_t)n * TOPK + k] = p;
        }
    }
    __syncthreads();

    float4* m4 = (float4*)(g_merged + (size_t)n * DIM);
    for (int i = tid; i < DIM / 4; i += 512) {
        float4 m = make_float4(0.f, 0.f, 0.f, 0.f);
        #pragma unroll
        for (int k = 0; k < TOPK; k++) {
            float p = s_probs[k];
            float4 v = s4[k * (DIM / 4) + i];
            m.x = fmaf(p, v.x, m.x); m.y = fmaf(p, v.y, m.y);
            m.z = fmaf(p, v.z, m.z); m.w = fmaf(p, v.w, m.w);
        }
        m4[i] = m;
    }
}

// ---------------------------------------------------------------------------
// Kernel B: fused MLP on bf16 tensor cores (wmma m16n16k16 -> native HMMA).
// CTA tile 128x128, 8 warps (2Mx4N), warp tile 64x32, K-chunk 32,
// double-buffered smem with register prefetch (one sync per iter).
// ---------------------------------------------------------------------------
#define SSTRIDE 40                 // halves per row (32 data + 8 pad), 80B
#define TILE_H  (128 * SSTRIDE)    // halves per tile

__global__ __launch_bounds__(256) void gemm_kernel(
    const float* __restrict__ hidden,
    const float* __restrict__ mW1,
    const float* __restrict__ mb1,
    const float* __restrict__ mW2)
{
    // 2 stages x (A + B) bf16 tiles = 40 KB; epilogue reuses as float scratch
    __shared__ __align__(16) char smem_raw[2 * 2 * TILE_H * 2];
    __nv_bfloat16* smem_h = (__nv_bfloat16*)smem_raw;

    const int tid  = threadIdx.x;
    const int wid  = tid >> 5, lane = tid & 31;
    const int rowTile = blockIdx.x;     // 0..15
    const int dTile   = blockIdx.y;     // 0..7
    const int warpM = wid >> 2;         // 0..1
    const int warpN = wid & 3;          // 0..3

    const int r  = tid >> 1;            // 0..127 (row this thread loads)
    const int kq = tid & 1;             // 0..1   (16-float chunk within K=32)

    wmma::fragment<wmma::accumulator, 16, 16, 16, float> c[4][2];
    #pragma unroll
    for (int mi = 0; mi < 4; mi++)
        #pragma unroll
        for (int ni = 0; ni < 2; ni++)
            wmma::fill_fragment(c[mi][ni], 0.f);

    // Each thread loads 16 floats of A and 16 of B per iteration (4 float4 each).
    float4 pva[4], pvb[4];

    const size_t arowbase = (size_t)(rowTile * 128 + r) * DIM;
    const size_t browbase = (size_t)(dTile * 128 + r) * KTOT;

    auto load_tiles = [&](int it) {
        const int k0 = it * 32;
        const float* Aseg = (k0 < DIM) ? (hidden + arowbase + k0)
                                       : (g_merged + arowbase + (k0 - DIM));
        const float* Bseg = mW1 + browbase + k0;
        #pragma unroll
        for (int q = 0; q < 4; q++) {
            pva[q] = *(const float4*)(Aseg + kq * 16 + q * 4);
            pvb[q] = *(const float4*)(Bseg + kq * 16 + q * 4);
        }
    };
    auto store_tiles = [&](int buf) {
        __nv_bfloat16* As = smem_h + buf * 2 * TILE_H;
        __nv_bfloat16* Bs = As + TILE_H;
        uint2 ua[2], ub[2];
        #pragma unroll
        for (int q = 0; q < 2; q++) {
            __nv_bfloat162 a0 = __floats2bfloat162_rn(pva[2*q].x,   pva[2*q].y);
            __nv_bfloat162 a1 = __floats2bfloat162_rn(pva[2*q].z,   pva[2*q].w);
            __nv_bfloat162 a2 = __floats2bfloat162_rn(pva[2*q+1].x, pva[2*q+1].y);
            __nv_bfloat162 a3 = __floats2bfloat162_rn(pva[2*q+1].z, pva[2*q+1].w);
            ua[q].x = *(unsigned*)&a0; ua[q].y = *(unsigned*)&a1;
            ub[q].x = *(unsigned*)&a2; ub[q].y = *(unsigned*)&a3;
            __nv_bfloat162 b0 = __floats2bfloat162_rn(pvb[2*q].x,   pvb[2*q].y);
            __nv_bfloat162 b1 = __floats2bfloat162_rn(pvb[2*q].z,   pvb[2*q].w);
            __nv_bfloat162 b2 = __floats2bfloat162_rn(pvb[2*q+1].x, pvb[2*q+1].y);
            __nv_bfloat162 b3 = __floats2bfloat162_rn(pvb[2*q+1].z, pvb[2*q+1].w);
            uint2 vb0; vb0.x = *(unsigned*)&b0; vb0.y = *(unsigned*)&b1;
            uint2 vb1; vb1.x = *(unsigned*)&b2; vb1.y = *(unsigned*)&b3;
            *(uint2*)(As + r * SSTRIDE + kq * 16 + q * 8)     = ua[q];
            *(uint2*)(As + r * SSTRIDE + kq * 16 + q * 8 + 4) = ub[q];
            *(uint2*)(Bs + r * SSTRIDE + kq * 16 + q * 8)     = vb0;
            *(uint2*)(Bs + r * SSTRIDE + kq * 16 + q * 8 + 4) = vb1;
        }
    };

    load_tiles(0);
    int buf = 0;
    for (int it = 0; it < KTOT / 32; ++it) {
        store_tiles(buf);
        __syncthreads();
        if (it < KTOT / 32 - 1) load_tiles(it + 1);   // latency hides under MMA

        const __nv_bfloat16* As = smem_h + buf * 2 * TILE_H;
        const __nv_bfloat16* Bs = As + TILE_H;
        #pragma unroll
        for (int kk = 0; kk < 2; kk++) {
            wmma::fragment<wmma::matrix_a, 16, 16, 16, __nv_bfloat16, wmma::row_major> a[4];
            wmma::fragment<wmma::matrix_b, 16, 16, 16, __nv_bfloat16, wmma::col_major> b[2];
            #pragma unroll
            for (int mi = 0; mi < 4; mi++)
                wmma::load_matrix_sync(a[mi], As + (warpM * 64 + mi * 16) * SSTRIDE + kk * 16, SSTRIDE);
            #pragma unroll
            for (int ni = 0; ni < 2; ni++)
                wmma::load_matrix_sync(b[ni], Bs + (warpN * 32 + ni * 16) * SSTRIDE + kk * 16, SSTRIDE);
            #pragma unroll
            for (int mi = 0; mi < 4; mi++)
                #pragma unroll
                for (int ni = 0; ni < 2; ni++)
                    wmma::mma_sync(c[mi][ni], a[mi], b[ni], c[mi][ni]);
        }
        buf ^= 1;
    }
    __syncthreads();   // protect smem reuse by epilogue

    // Epilogue: frags -> smem scratch -> relu+dot(mW2) rowsum -> g_zpart.
    float* fbuf  = (float*)smem_raw;
    float* scr   = fbuf + wid * 320;        // [16][20] per warp
    float* zrows = fbuf + 8 * 320;          // [128][4]

    float zacc[4] = {0.f, 0.f, 0.f, 0.f};
    const int r16 = lane & 15, ch = (lane >> 4) * 8;
    #pragma unroll
    for (int mi = 0; mi < 4; mi++) {
        #pragma unroll
        for (int ni = 0; ni < 2; ni++) {
            wmma::store_matrix_sync(scr, c[mi][ni], 20, wmma::mem_row_major);
            __syncwarp();
            int gc0 = dTile * 128 + warpN * 32 + ni * 16 + ch;
            float z = 0.f;
            #pragma unroll
            for (int cc = 0; cc < 8; cc++) {
                float v = scr[r16 * 20 + ch + cc] + __ldg(&mb1[gc0 + cc]);
                z = fmaf(fmaxf(v, 0.f), __ldg(&mW2[gc0 + cc]), z);
            }
            z += __shfl_xor_sync(0xffffffffu, z, 16);
            zacc[mi] += z;          // valid in lanes 0..15
            __syncwarp();
        }
    }
    if (lane < 16) {
        #pragma unroll
        for (int mi = 0; mi < 4; mi++)
            zrows[(warpM * 64 + mi * 16 + lane) * 4 + warpN] = zacc[mi];
    }
    __syncthreads();
    if (tid < 128) {
        float z = zrows[tid * 4 + 0] + zrows[tid * 4 + 1]
                + zrows[tid * 4 + 2] + zrows[tid * 4 + 3];
        g_zpart[(size_t)(rowTile * 128 + tid) * DTILES + dTile] = z;
    }
}

// ---------------------------------------------------------------------------
// Kernel C: per-row output. One block per row, logits staged in 125KB smem.
// ---------------------------------------------------------------------------
__global__ __launch_bounds__(1024) void out_kernel(
    const float* __restrict__ logits,
    const void* __restrict__ tok,
    const float* __restrict__ mb2,
    float* __restrict__ out)
{
    const int n = blockIdx.x;
    extern __shared__ float slg[];                 // VOCAB floats
    __shared__ float sred[32];
    __shared__ float s_max, s_sum, s_m;
    __shared__ int   s_uidx[TOPK];
    __shared__ float s_uval[TOPK];
    __shared__ int   s_ucnt;

    const int tid  = threadIdx.x;
    const int lane = tid & 31, wid = tid >> 5;
    const float* lrow = logits + (size_t)n * VOCAB;
    float*       orow = out    + (size_t)n * VOCAB;

    float mx = -1e30f;
    const float4* l4 = (const float4*)lrow;
    float4*       s4 = (float4*)slg;
    for (int i = tid; i < VOCAB / 4; i += 1024) {
        float4 v = l4[i];
        s4[i] = v;
        mx = fmaxf(mx, fmaxf(fmaxf(v.x, v.y), fmaxf(v.z, v.w)));
    }
    #pragma unroll
    for (int o = 16; o > 0; o >>= 1)
        mx = fmaxf(mx, __shfl_xor_sync(0xffffffffu, mx, o));
    if (lane == 0) sred[wid] = mx;
    __syncthreads();
    if (tid < 32) {
        float v = sred[tid];
        #pragma unroll
        for (int o = 16; o > 0; o >>= 1)
            v = fmaxf(v, __shfl_xor_sync(0xffffffffu, v, o));
        if (tid == 0) s_max = v;
    }
    __syncthreads();

    float fm = s_max;
    float sm = 0.f;
    for (int i = tid; i < VOCAB; i += 1024)
        sm += expf(slg[i] - fm);
    #pragma unroll
    for (int o = 16; o > 0; o >>= 1)
        sm += __shfl_xor_sync(0xffffffffu, sm, o);
    __syncthreads();
    if (lane == 0) sred[wid] = sm;
    __syncthreads();
    if (tid < 32) {
        float v = sred[tid];
        #pragma unroll
        for (int o = 16; o > 0; o >>= 1)
            v += __shfl_xor_sync(0xffffffffu, v, o);
        if (tid == 0) s_sum = v;
    }

    if (tid == 0) {
        const int* t32 = (const int*)tok;
        int is64 = 1;
        #pragma unroll
        for (int k = 0; k < TOPK; k++)
            if (t32[2 * k + 1] != 0) is64 = 0;

        float z = mb2[0];
        #pragma unroll
        for (int j = 0; j < DTILES; j++) z += g_zpart[(size_t)n * DTILES + j];
        float m = 1.f / (1.f + expf(-z));
        s_m = m;

        const long long* t64 = (const long long*)tok;
        int cnt = 0;
        #pragma unroll
        for (int k = 0; k < TOPK; k++) {
            int idx = is64 ? (int)t64[(size_t)n * TOPK + k]
                           : t32[(size_t)n * TOPK + k];
            idx = min(max(idx, 0), VOCAB - 1);
            float val = m * g_probs[(size_t)n * TOPK + k];
            int j = 0;
            for (; j < cnt; j++) if (s_uidx[j] == idx) break;
            if (j < cnt) s_uval[j] += val;
            else { s_uidx[cnt] = idx; s_uval[cnt] = val; cnt++; }
        }
        s_ucnt = cnt;
    }
    __syncthreads();

    const float logc = logf((1.f - s_m) / s_sum);
    for (int i = tid; i < VOCAB / 4; i += 1024) {
        float4 v = s4[i];
        v.x = v.x - fm + logc;
        v.y = v.y - fm + logc;
        v.z = v.z - fm + logc;
        v.w = v.w - fm + logc;
        ((float4*)orow)[i] = v;
    }
    __syncthreads();

    if (tid < s_ucnt) {
        int vi = s_uidx[tid];
        float p = expf(slg[vi] - fm) / s_sum;
        orow[vi] = logf((1.f - s_m) * p + s_uval[tid]);
    }
}

// ---------------------------------------------------------------------------
extern "C" void kernel_launch(void* const* d_in, const int* in_sizes, int n_in,
                              void* d_out, int out_size)
{
    int i_logits = -1, i_sh = -1, i_bW = -1;
    int p2m[2] = {-1, -1};  int n2m = 0;
    int p32k[2] = {-1, -1}; int n32k = 0;
    int p1k[2] = {-1, -1};  int n1k = 0;
    int p1[2] = {-1, -1};   int n1 = 0;

    for (int i = 0; i < n_in; i++) {
        switch (in_sizes[i]) {
            case 65536000: i_logits = i; break;
            case 33554432: i_sh = i; break;
            case 2048:     i_bW = i; break;
            case 2097152:  if (n2m < 2) p2m[n2m++] = i; break;
            case 32768:    if (n32k < 2) p32k[n32k++] = i; break;
            case 1024:     if (n1k < 2) p1k[n1k++] = i; break;
            case 1:        if (n1 < 2) p1[n1++] = i; break;
            default: break;
        }
    }
    const bool alpha = (i_bW >= 0 && i_logits >= 0 && i_bW < i_logits);
    const int i_hidden = p2m[0],  i_mW1 = p2m[1];
    const int i_dist   = p32k[0], i_tok = p32k[1];
    const int i_bb     = p1[0],   i_mb2 = p1[1];
    const int i_mb1    = alpha ? p1k[1] : p1k[0];
    const int i_mW2    = alpha ? p1k[0] : p1k[1];

    const float* hidden = (const float*)d_in[i_hidden];
    const float* logits = (const float*)d_in[i_logits];
    const float* dist   = (const float*)d_in[i_dist];
    const float* sh     = (const float*)d_in[i_sh];
    const void*  tok    = d_in[i_tok];
    const float* bW     = (const float*)d_in[i_bW];
    const float* bb     = (const float*)d_in[i_bb];
    const float* mW1    = (const float*)d_in[i_mW1];
    const float* mb1    = (const float*)d_in[i_mb1];
    const float* mW2    = (const float*)d_in[i_mW2];
    const float* mb2    = (const float*)d_in[i_mb2];
    float*       out    = (float*)d_out;

    const int smA = TOPK * DIM * sizeof(float);   // 64 KB
    const int smC = VOCAB * sizeof(float);        // 125 KB
    cudaFuncSetAttribute(prep_kernel, cudaFuncAttributeMaxDynamicSharedMemorySize, smA);
    cudaFuncSetAttribute(out_kernel,  cudaFuncAttributeMaxDynamicSharedMemorySize, smC);

    prep_kernel<<<N_ROWS, 512, smA>>>(hidden, dist, sh, bW, bb);
    gemm_kernel<<<dim3(16, 8), 256>>>(hidden, mW1, mb1, mW2);
    out_kernel<<<N_ROWS, 1024, smC>>>(logits, tok, mb2, out);
}